// round 4
// baseline (speedup 1.0000x reference)
#include <cuda_runtime.h>
#include <cstdint>

#define N_NODES 16384
#define IN_F    256
#define OUT_F   64

// Intermediate h = x@W + b  (16384 x 64 fp32 = 4 MB) as device global (no allocs allowed)
__device__ float g_h[N_NODES * OUT_F];

// ---------------------------------------------------------------------------
// Kernel A: h = x @ W + b   (fp32, register-tiled; small: 537 MFLOP)
// BM=128 rows/block, 128 threads, 8x8 register tile per thread, BK=32
// ---------------------------------------------------------------------------
__global__ __launch_bounds__(128) void linear_kernel(
    const float* __restrict__ x, const float* __restrict__ W,
    const float* __restrict__ b)
{
    __shared__ float xs_t[32][132];   // x tile transposed [k][m], padded
    __shared__ float Ws[32][68];      // W tile [k][n], padded

    const int tid  = threadIdx.x;
    const int rb   = blockIdx.x * 128;
    const int trow = tid >> 3;        // 0..15
    const int tcol = tid & 7;         // 0..7
    const int r0   = trow * 8;
    const int c0   = tcol * 8;

    float acc[8][8];
#pragma unroll
    for (int i = 0; i < 8; ++i)
#pragma unroll
        for (int j = 0; j < 8; ++j) acc[i][j] = 0.f;

    for (int kt = 0; kt < IN_F / 32; ++kt) {
        // load x tile 128x32 and transpose into smem
#pragma unroll
        for (int i = 0; i < 8; ++i) {
            int e = i * 128 + tid;
            int row = e >> 3;
            int c4  = e & 7;
            float4 v = *(const float4*)(x + (size_t)(rb + row) * IN_F + kt * 32 + c4 * 4);
            xs_t[c4 * 4 + 0][row] = v.x;
            xs_t[c4 * 4 + 1][row] = v.y;
            xs_t[c4 * 4 + 2][row] = v.z;
            xs_t[c4 * 4 + 3][row] = v.w;
        }
        // load W tile 32x64
#pragma unroll
        for (int i = 0; i < 4; ++i) {
            int e = i * 128 + tid;
            int row = e >> 4;
            int c4  = e & 15;
            *(float4*)&Ws[row][c4 * 4] =
                *(const float4*)(W + (size_t)(kt * 32 + row) * OUT_F + c4 * 4);
        }
        __syncthreads();

#pragma unroll
        for (int k = 0; k < 32; ++k) {
            float4 xa = *(const float4*)&xs_t[k][r0];
            float4 xb = *(const float4*)&xs_t[k][r0 + 4];
            float4 wa = *(const float4*)&Ws[k][c0];
            float4 wb = *(const float4*)&Ws[k][c0 + 4];
            float xr[8] = {xa.x, xa.y, xa.z, xa.w, xb.x, xb.y, xb.z, xb.w};
            float wr[8] = {wa.x, wa.y, wa.z, wa.w, wb.x, wb.y, wb.z, wb.w};
#pragma unroll
            for (int i = 0; i < 8; ++i)
#pragma unroll
                for (int j = 0; j < 8; ++j) acc[i][j] += xr[i] * wr[j];
        }
        __syncthreads();
    }

    float bb[8];
#pragma unroll
    for (int j = 0; j < 8; ++j) bb[j] = b[c0 + j];

#pragma unroll
    for (int i = 0; i < 8; ++i) {
        float4 v0, v1;
        v0.x = acc[i][0] + bb[0]; v0.y = acc[i][1] + bb[1];
        v0.z = acc[i][2] + bb[2]; v0.w = acc[i][3] + bb[3];
        v1.x = acc[i][4] + bb[4]; v1.y = acc[i][5] + bb[5];
        v1.z = acc[i][6] + bb[6]; v1.w = acc[i][7] + bb[7];
        float* dst = g_h + (size_t)(rb + r0 + i) * OUT_F + c0;
        *(float4*)dst       = v0;
        *(float4*)(dst + 4) = v1;
    }
}

// ---------------------------------------------------------------------------
// Kernel B: out = relu(adj @ h)   tf32 mma.sync m16n8k8, fp32 accumulate
// BM=128, BN=64(full), BK=32; 128 threads = 4 warps, warp tile 64x32
// 2-stage cp.async pipeline; XOR-swizzled smem (no padding, 48KB exactly)
// ---------------------------------------------------------------------------
__device__ __forceinline__ uint32_t f2tf32(float f) {
    uint32_t u;
    asm("cvt.rna.tf32.f32 %0, %1;" : "=r"(u) : "f"(f));
    return u;
}
__device__ __forceinline__ void cp_async16(void* sm, const void* gm) {
    uint32_t s = (uint32_t)__cvta_generic_to_shared(sm);
    asm volatile("cp.async.cg.shared.global [%0], [%1], 16;" :: "r"(s), "l"(gm));
}

#define MMA_TF32(d, a, bf)                                                    \
    asm volatile(                                                             \
        "mma.sync.aligned.m16n8k8.row.col.f32.tf32.tf32.f32 "                 \
        "{%0,%1,%2,%3}, {%4,%5,%6,%7}, {%8,%9}, {%0,%1,%2,%3};"               \
        : "+f"(d[0]), "+f"(d[1]), "+f"(d[2]), "+f"(d[3])                      \
        : "r"(a[0]), "r"(a[1]), "r"(a[2]), "r"(a[3]), "r"(bf[0]), "r"(bf[1]))

__global__ __launch_bounds__(128) void agg_kernel(
    const float* __restrict__ adj, float* __restrict__ out)
{
    // As: 128x32 f32 per stage, stored as float4 with c4 ^= (row&7) swizzle
    // Hs: 32x64  f32 per stage, stored as float4 with c4 ^= ((k&3)<<1) swizzle
    __shared__ float4 As4[2][128][8];   // 32 KB
    __shared__ float4 Hs4[2][32][16];   // 16 KB

    const int tid   = threadIdx.x;
    const int lane  = tid & 31;
    const int wid   = tid >> 5;
    const int warpM = wid & 1;          // 0..1 -> 64 rows each
    const int warpN = wid >> 1;         // 0..1 -> 32 cols each
    const int g     = lane >> 2;        // groupID 0..7
    const int tig   = lane & 3;         // thread-in-group 0..3

    const size_t rowBase = (size_t)blockIdx.x * 128;
    const float* gA0 = adj + rowBase * N_NODES;

    float acc[4][4][4];
#pragma unroll
    for (int mt = 0; mt < 4; ++mt)
#pragma unroll
        for (int nt = 0; nt < 4; ++nt)
#pragma unroll
            for (int e = 0; e < 4; ++e) acc[mt][nt][e] = 0.f;

    const int NK = N_NODES / 32;  // 512

    auto issue = [&](int kt) {
        const int stage = kt & 1;
        const float* gA = gA0 + kt * 32;
#pragma unroll
        for (int i = 0; i < 8; ++i) {          // 128x32 = 1024 float4
            int e   = i * 128 + tid;
            int row = e >> 3;
            int c4  = e & 7;
            cp_async16(&As4[stage][row][c4 ^ (row & 7)],
                       gA + (size_t)row * N_NODES + c4 * 4);
        }
        const float* gH = g_h + (size_t)kt * 32 * OUT_F;
#pragma unroll
        for (int i = 0; i < 4; ++i) {          // 32x64 = 512 float4
            int e  = i * 128 + tid;
            int k  = e >> 4;
            int c4 = e & 15;
            cp_async16(&Hs4[stage][k][c4 ^ ((k & 3) << 1)],
                       gH + k * OUT_F + c4 * 4);
        }
    };

    issue(0);
    asm volatile("cp.async.commit_group;");

    for (int kt = 0; kt < NK; ++kt) {
        asm volatile("cp.async.wait_group 0;");
        __syncthreads();
        if (kt + 1 < NK) {
            issue(kt + 1);
            asm volatile("cp.async.commit_group;");
        }

        const int stage = kt & 1;
        const float* As = (const float*)As4[stage];  // swizzled [128][32]
        const float* Hs = (const float*)Hs4[stage];  // swizzled [32][64]

#pragma unroll
        for (int ks = 0; ks < 4; ++ks) {
            const int kb = ks * 8;
            // A fragments: element (row,k) lives at word
            //   row*32 + ((k>>2)^(row&7))*4 + (k&3)
            uint32_t afr[4][4];
#pragma unroll
            for (int mt = 0; mt < 4; ++mt) {
                int r  = warpM * 64 + mt * 16 + g;
                int k0 = kb + tig;
                int k1 = k0 + 4;
                afr[mt][0] = f2tf32(As[r * 32       + (((k0 >> 2) ^ (r & 7)) << 2) + (k0 & 3)]);
                afr[mt][1] = f2tf32(As[(r + 8) * 32 + (((k0 >> 2) ^ (r & 7)) << 2) + (k0 & 3)]);
                afr[mt][2] = f2tf32(As[r * 32       + (((k1 >> 2) ^ (r & 7)) << 2) + (k1 & 3)]);
                afr[mt][3] = f2tf32(As[(r + 8) * 32 + (((k1 >> 2) ^ (r & 7)) << 2) + (k1 & 3)]);
            }
            // B fragments: element (k,n) lives at word  k*64 + (n ^ ((k&3)<<3))
            uint32_t bfr[4][2];
#pragma unroll
            for (int nt = 0; nt < 4; ++nt) {
                int n  = warpN * 32 + nt * 8 + g;
                int k0 = kb + tig;
                int k1 = k0 + 4;
                bfr[nt][0] = f2tf32(Hs[k0 * 64 + (n ^ ((k0 & 3) << 3))]);
                bfr[nt][1] = f2tf32(Hs[k1 * 64 + (n ^ ((k1 & 3) << 3))]);
            }
#pragma unroll
            for (int mt = 0; mt < 4; ++mt)
#pragma unroll
                for (int nt = 0; nt < 4; ++nt)
                    MMA_TF32(acc[mt][nt], afr[mt], bfr[nt]);
        }
    }

    // epilogue: relu + store (c0,c1)->(g, 2*tig), (c2,c3)->(g+8, 2*tig)
#pragma unroll
    for (int mt = 0; mt < 4; ++mt) {
        size_t r = rowBase + warpM * 64 + mt * 16 + g;
#pragma unroll
        for (int nt = 0; nt < 4; ++nt) {
            int c = warpN * 32 + nt * 8 + tig * 2;
            float2 v0, v1;
            v0.x = fmaxf(acc[mt][nt][0], 0.f);
            v0.y = fmaxf(acc[mt][nt][1], 0.f);
            v1.x = fmaxf(acc[mt][nt][2], 0.f);
            v1.y = fmaxf(acc[mt][nt][3], 0.f);
            *(float2*)&out[r * OUT_F + c]       = v0;
            *(float2*)&out[(r + 8) * OUT_F + c] = v1;
        }
    }
}

// ---------------------------------------------------------------------------
extern "C" void kernel_launch(void* const* d_in, const int* in_sizes, int n_in,
                              void* d_out, int out_size)
{
    const float* x   = (const float*)d_in[0];   // [16384, 256]
    const float* adj = (const float*)d_in[1];   // [16384, 16384]
    const float* W   = (const float*)d_in[2];   // [256, 64]
    const float* b   = (const float*)d_in[3];   // [64]
    float* out = (float*)d_out;                 // [16384, 64]

    linear_kernel<<<N_NODES / 128, 128>>>(x, W, b);
    agg_kernel<<<N_NODES / 128, 128>>>(adj, out);
}

// round 5
// speedup vs baseline: 1.4763x; 1.4763x over previous
#include <cuda_runtime.h>
#include <cstdint>

#define N_NODES 16384
#define IN_F    256
#define OUT_F   64

// Intermediate h = x@W + b  (16384 x 64 fp32 = 4 MB) as device global
__device__ float g_h[N_NODES * OUT_F];

// ---------------------------------------------------------------------------
// Kernel A: h = x @ W + b   (fp32, register-tiled)
// BM=64 rows/block (grid=256), 128 threads, 4x8 register tile, BK=32
// ---------------------------------------------------------------------------
__global__ __launch_bounds__(128) void linear_kernel(
    const float* __restrict__ x, const float* __restrict__ W,
    const float* __restrict__ b)
{
    __shared__ float xs_t[32][68];    // x tile transposed [k][m], padded
    __shared__ float Ws[32][68];      // W tile [k][n], padded

    const int tid  = threadIdx.x;
    const int rb   = blockIdx.x * 64;
    const int trow = tid >> 3;        // 0..15
    const int tcol = tid & 7;         // 0..7
    const int r0   = trow * 4;
    const int c0   = tcol * 8;

    float acc[4][8];
#pragma unroll
    for (int i = 0; i < 4; ++i)
#pragma unroll
        for (int j = 0; j < 8; ++j) acc[i][j] = 0.f;

    for (int kt = 0; kt < IN_F / 32; ++kt) {
        // load x tile 64x32 and transpose into smem
#pragma unroll
        for (int i = 0; i < 4; ++i) {
            int e = i * 128 + tid;
            int row = e >> 3;
            int c4  = e & 7;
            float4 v = *(const float4*)(x + (size_t)(rb + row) * IN_F + kt * 32 + c4 * 4);
            xs_t[c4 * 4 + 0][row] = v.x;
            xs_t[c4 * 4 + 1][row] = v.y;
            xs_t[c4 * 4 + 2][row] = v.z;
            xs_t[c4 * 4 + 3][row] = v.w;
        }
        // load W tile 32x64
#pragma unroll
        for (int i = 0; i < 4; ++i) {
            int e = i * 128 + tid;
            int row = e >> 4;
            int c4  = e & 15;
            *(float4*)&Ws[row][c4 * 4] =
                *(const float4*)(W + (size_t)(kt * 32 + row) * OUT_F + c4 * 4);
        }
        __syncthreads();

#pragma unroll
        for (int k = 0; k < 32; ++k) {
            float4 xa = *(const float4*)&xs_t[k][r0];
            float4 wa = *(const float4*)&Ws[k][c0];
            float4 wb = *(const float4*)&Ws[k][c0 + 4];
            float xr[4] = {xa.x, xa.y, xa.z, xa.w};
            float wr[8] = {wa.x, wa.y, wa.z, wa.w, wb.x, wb.y, wb.z, wb.w};
#pragma unroll
            for (int i = 0; i < 4; ++i)
#pragma unroll
                for (int j = 0; j < 8; ++j) acc[i][j] += xr[i] * wr[j];
        }
        __syncthreads();
    }

    float bb[8];
#pragma unroll
    for (int j = 0; j < 8; ++j) bb[j] = b[c0 + j];

#pragma unroll
    for (int i = 0; i < 4; ++i) {
        float4 v0, v1;
        v0.x = acc[i][0] + bb[0]; v0.y = acc[i][1] + bb[1];
        v0.z = acc[i][2] + bb[2]; v0.w = acc[i][3] + bb[3];
        v1.x = acc[i][4] + bb[4]; v1.y = acc[i][5] + bb[5];
        v1.z = acc[i][6] + bb[6]; v1.w = acc[i][7] + bb[7];
        float* dst = g_h + (size_t)(rb + r0 + i) * OUT_F + c0;
        *(float4*)dst       = v0;
        *(float4*)(dst + 4) = v1;
    }
}

// ---------------------------------------------------------------------------
// Kernel B: out = relu(adj @ h)   tf32 mma.sync m16n8k8, fp32 accumulate
// BM=128, BN=64, BK=64; 256 threads = 8 warps (warp tile 32x32)
// 3-stage cp.async pipeline in 144KB dynamic smem; XOR-swizzled (no padding)
// ---------------------------------------------------------------------------
#define STAGES 3
#define BK     64
// per-stage: A 128x64 f32 = 32KB, H 64x64 f32 = 16KB
#define A_STAGE_F4 (128 * 16)
#define H_STAGE_F4 (64 * 16)
#define SMEM_BYTES (STAGES * (A_STAGE_F4 + H_STAGE_F4) * 16)

__device__ __forceinline__ uint32_t f2tf32(float f) {
    uint32_t u;
    asm("cvt.rna.tf32.f32 %0, %1;" : "=r"(u) : "f"(f));
    return u;
}
__device__ __forceinline__ void cp_async16(void* sm, const void* gm) {
    uint32_t s = (uint32_t)__cvta_generic_to_shared(sm);
    asm volatile("cp.async.cg.shared.global [%0], [%1], 16;" :: "r"(s), "l"(gm));
}

#define MMA_TF32(d, a, bf)                                                    \
    asm volatile(                                                             \
        "mma.sync.aligned.m16n8k8.row.col.f32.tf32.tf32.f32 "                 \
        "{%0,%1,%2,%3}, {%4,%5,%6,%7}, {%8,%9}, {%0,%1,%2,%3};"               \
        : "+f"(d[0]), "+f"(d[1]), "+f"(d[2]), "+f"(d[3])                      \
        : "r"(a[0]), "r"(a[1]), "r"(a[2]), "r"(a[3]), "r"(bf[0]), "r"(bf[1]))

__global__ __launch_bounds__(256) void agg_kernel(
    const float* __restrict__ adj, float* __restrict__ out)
{
    extern __shared__ float4 smem[];
    // layout: [STAGES][A_STAGE_F4] then [STAGES][H_STAGE_F4]
    float4* As4base = smem;
    float4* Hs4base = smem + STAGES * A_STAGE_F4;

    const int tid   = threadIdx.x;
    const int lane  = tid & 31;
    const int wid   = tid >> 5;
    const int warpM = wid & 3;          // 0..3 -> 32 rows each
    const int warpN = wid >> 2;         // 0..1 -> 32 cols each
    const int g     = lane >> 2;        // groupID 0..7
    const int tig   = lane & 3;         // thread-in-group 0..3

    const size_t rowBase = (size_t)blockIdx.x * 128;
    const float* gA0 = adj + rowBase * N_NODES;

    float acc[2][4][4];
#pragma unroll
    for (int mt = 0; mt < 2; ++mt)
#pragma unroll
        for (int nt = 0; nt < 4; ++nt)
#pragma unroll
            for (int e = 0; e < 4; ++e) acc[mt][nt][e] = 0.f;

    const int NK = N_NODES / BK;        // 256

    auto issue = [&](int kt) {
        const int stage = kt % STAGES;
        float4* As4 = As4base + stage * A_STAGE_F4;   // [128][16] swizzled
        float4* Hs4 = Hs4base + stage * H_STAGE_F4;   // [64][16]  swizzled
        const float* gA = gA0 + kt * BK;
#pragma unroll
        for (int i = 0; i < 8; ++i) {                 // 128x64 = 2048 float4
            int e   = i * 256 + tid;
            int row = e >> 4;
            int c4  = e & 15;
            cp_async16(&As4[row * 16 + (c4 ^ (row & 7))],
                       gA + (size_t)row * N_NODES + c4 * 4);
        }
        const float* gH = g_h + (size_t)kt * BK * OUT_F;
#pragma unroll
        for (int i = 0; i < 4; ++i) {                 // 64x64 = 1024 float4
            int e  = i * 256 + tid;
            int k  = e >> 4;
            int c4 = e & 15;
            cp_async16(&Hs4[k * 16 + (c4 ^ ((k & 3) << 1))],
                       gH + k * OUT_F + c4 * 4);
        }
    };

    // prologue: prefetch 2 stages
    issue(0); asm volatile("cp.async.commit_group;");
    issue(1); asm volatile("cp.async.commit_group;");

    for (int kt = 0; kt < NK; ++kt) {
        asm volatile("cp.async.wait_group 1;");
        __syncthreads();
        if (kt + 2 < NK) issue(kt + 2);
        asm volatile("cp.async.commit_group;");       // uniform group count

        const int stage = kt % STAGES;
        const float* As = (const float*)(As4base + stage * A_STAGE_F4); // [128][64] swz
        const float* Hs = (const float*)(Hs4base + stage * H_STAGE_F4); // [64][64]  swz

#pragma unroll
        for (int ks = 0; ks < 8; ++ks) {
            const int kb = ks * 8;
            const int k0 = kb + tig;
            const int k1 = k0 + 4;
            // A fragments: element (r,k) at word r*64 + (((k>>2)^(r&7))<<2) + (k&3)
            uint32_t afr[2][4];
#pragma unroll
            for (int mt = 0; mt < 2; ++mt) {
                int r = warpM * 32 + mt * 16 + g;
                afr[mt][0] = f2tf32(As[r * 64       + (((k0 >> 2) ^ (r & 7)) << 2) + (k0 & 3)]);
                afr[mt][1] = f2tf32(As[(r + 8) * 64 + (((k0 >> 2) ^ (r & 7)) << 2) + (k0 & 3)]);
                afr[mt][2] = f2tf32(As[r * 64       + (((k1 >> 2) ^ (r & 7)) << 2) + (k1 & 3)]);
                afr[mt][3] = f2tf32(As[(r + 8) * 64 + (((k1 >> 2) ^ (r & 7)) << 2) + (k1 & 3)]);
            }
            // B fragments: element (k,n) at word k*64 + (n ^ ((k&3)<<3))
            uint32_t bfr[4][2];
#pragma unroll
            for (int nt = 0; nt < 4; ++nt) {
                int n = warpN * 32 + nt * 8 + g;
                bfr[nt][0] = f2tf32(Hs[k0 * 64 + (n ^ ((k0 & 3) << 3))]);
                bfr[nt][1] = f2tf32(Hs[k1 * 64 + (n ^ ((k1 & 3) << 3))]);
            }
#pragma unroll
            for (int mt = 0; mt < 2; ++mt)
#pragma unroll
                for (int nt = 0; nt < 4; ++nt)
                    MMA_TF32(acc[mt][nt], afr[mt], bfr[nt]);
        }
    }

    // epilogue: relu + store. (c0,c1)->(row g, col 2*tig), (c2,c3)->(row g+8)
#pragma unroll
    for (int mt = 0; mt < 2; ++mt) {
        size_t r = rowBase + warpM * 32 + mt * 16 + g;
#pragma unroll
        for (int nt = 0; nt < 4; ++nt) {
            int c = warpN * 32 + nt * 8 + tig * 2;
            float2 v0, v1;
            v0.x = fmaxf(acc[mt][nt][0], 0.f);
            v0.y = fmaxf(acc[mt][nt][1], 0.f);
            v1.x = fmaxf(acc[mt][nt][2], 0.f);
            v1.y = fmaxf(acc[mt][nt][3], 0.f);
            *(float2*)&out[r * OUT_F + c]       = v0;
            *(float2*)&out[(r + 8) * OUT_F + c] = v1;
        }
    }
}

// ---------------------------------------------------------------------------
extern "C" void kernel_launch(void* const* d_in, const int* in_sizes, int n_in,
                              void* d_out, int out_size)
{
    const float* x   = (const float*)d_in[0];   // [16384, 256]
    const float* adj = (const float*)d_in[1];   // [16384, 16384]
    const float* W   = (const float*)d_in[2];   // [256, 64]
    const float* b   = (const float*)d_in[3];   // [64]
    float* out = (float*)d_out;                 // [16384, 64]

    cudaFuncSetAttribute(agg_kernel,
                         cudaFuncAttributeMaxDynamicSharedMemorySize, SMEM_BYTES);

    linear_kernel<<<N_NODES / 64, 128>>>(x, W, b);
    agg_kernel<<<N_NODES / 128, 256, SMEM_BYTES>>>(adj, out);
}

// round 8
// speedup vs baseline: 1.5860x; 1.0743x over previous
#include <cuda_runtime.h>
#include <cstdint>

#define N_NODES 16384
#define IN_F    256
#define OUT_F   64

// Intermediate h = x@W + b, pre-rounded to tf32 bit pattern (low 13 bits zero)
__device__ float g_h[N_NODES * OUT_F];

__device__ __forceinline__ uint32_t f2tf32(float f) {
    uint32_t u;
    asm("cvt.rna.tf32.f32 %0, %1;" : "=r"(u) : "f"(f));
    return u;
}

// ---------------------------------------------------------------------------
// Kernel A: h = tf32_round(x @ W + b)
// BM=64 rows/block (grid=256), 128 threads, 4x8 register tile, BK=32
// ---------------------------------------------------------------------------
__global__ __launch_bounds__(128) void linear_kernel(
    const float* __restrict__ x, const float* __restrict__ W,
    const float* __restrict__ b)
{
    __shared__ float xs_t[32][68];
    __shared__ float Ws[32][68];

    const int tid  = threadIdx.x;
    const int rb   = blockIdx.x * 64;
    const int trow = tid >> 3;
    const int tcol = tid & 7;
    const int r0   = trow * 4;
    const int c0   = tcol * 8;

    float acc[4][8];
#pragma unroll
    for (int i = 0; i < 4; ++i)
#pragma unroll
        for (int j = 0; j < 8; ++j) acc[i][j] = 0.f;

    for (int kt = 0; kt < IN_F / 32; ++kt) {
#pragma unroll
        for (int i = 0; i < 4; ++i) {
            int e = i * 128 + tid;
            int row = e >> 3;
            int c4  = e & 7;
            float4 v = *(const float4*)(x + (size_t)(rb + row) * IN_F + kt * 32 + c4 * 4);
            xs_t[c4 * 4 + 0][row] = v.x;
            xs_t[c4 * 4 + 1][row] = v.y;
            xs_t[c4 * 4 + 2][row] = v.z;
            xs_t[c4 * 4 + 3][row] = v.w;
        }
#pragma unroll
        for (int i = 0; i < 4; ++i) {
            int e = i * 128 + tid;
            int row = e >> 4;
            int c4  = e & 15;
            *(float4*)&Ws[row][c4 * 4] =
                *(const float4*)(W + (size_t)(kt * 32 + row) * OUT_F + c4 * 4);
        }
        __syncthreads();

#pragma unroll
        for (int k = 0; k < 32; ++k) {
            float4 xa = *(const float4*)&xs_t[k][r0];
            float4 wa = *(const float4*)&Ws[k][c0];
            float4 wb = *(const float4*)&Ws[k][c0 + 4];
            float xr[4] = {xa.x, xa.y, xa.z, xa.w};
            float wr[8] = {wa.x, wa.y, wa.z, wa.w, wb.x, wb.y, wb.z, wb.w};
#pragma unroll
            for (int i = 0; i < 4; ++i)
#pragma unroll
                for (int j = 0; j < 8; ++j) acc[i][j] += xr[i] * wr[j];
        }
        __syncthreads();
    }

    float bb[8];
#pragma unroll
    for (int j = 0; j < 8; ++j) bb[j] = b[c0 + j];

#pragma unroll
    for (int i = 0; i < 4; ++i) {
        float v[8];
#pragma unroll
        for (int j = 0; j < 8; ++j)
            v[j] = __uint_as_float(f2tf32(acc[i][j] + bb[j]));   // pre-round to tf32
        float* dst = g_h + (size_t)(rb + r0 + i) * OUT_F + c0;
        *(float4*)dst       = make_float4(v[0], v[1], v[2], v[3]);
        *(float4*)(dst + 4) = make_float4(v[4], v[5], v[6], v[7]);
    }
}

// ---------------------------------------------------------------------------
// Kernel B: out = relu(adj @ h)   tf32 mma.sync m16n8k8, fp32 accumulate
// BM=64, BN=64, BK=64; 256 threads = 8 warps: 2(M) x 2(N) x 2(split-K)
// warp tile 32x32 over 32 k per iter; 3-stage cp.async, 96KB smem, 2 CTAs/SM
// ---------------------------------------------------------------------------
#define STAGES 3
#define BK     64
#define A_STAGE_F4 (64 * 16)   // 64x64 f32 = 16KB
#define H_STAGE_F4 (64 * 16)   // 64x64 f32 = 16KB
#define SMEM_BYTES (STAGES * (A_STAGE_F4 + H_STAGE_F4) * 16)   // 96KB

__device__ __forceinline__ void cp_async16(void* sm, const void* gm) {
    uint32_t s = (uint32_t)__cvta_generic_to_shared(sm);
    asm volatile("cp.async.cg.shared.global [%0], [%1], 16;" :: "r"(s), "l"(gm));
}

#define MMA_TF32(d, a, bf)                                                    \
    asm volatile(                                                             \
        "mma.sync.aligned.m16n8k8.row.col.f32.tf32.tf32.f32 "                 \
        "{%0,%1,%2,%3}, {%4,%5,%6,%7}, {%8,%9}, {%0,%1,%2,%3};"               \
        : "+f"(d[0]), "+f"(d[1]), "+f"(d[2]), "+f"(d[3])                      \
        : "r"(a[0]), "r"(a[1]), "r"(a[2]), "r"(a[3]), "r"(bf[0]), "r"(bf[1]))

__global__ __launch_bounds__(256, 2) void agg_kernel(
    const float* __restrict__ adj, float* __restrict__ out)
{
    extern __shared__ float4 smem[];
    float4* As4base = smem;                       // [STAGES][64][16] swizzled
    float4* Hs4base = smem + STAGES * A_STAGE_F4; // [STAGES][64][16] swizzled

    const int tid   = threadIdx.x;
    const int lane  = tid & 31;
    const int wid   = tid >> 5;
    const int wm    = wid & 1;          // M half: 0..1 (32 rows)
    const int wn    = (wid >> 1) & 1;   // N half: 0..1 (32 cols)
    const int kh    = wid >> 2;         // K half: 0..1 (32 k per iter)
    const int g     = lane >> 2;        // 0..7
    const int tig   = lane & 3;         // 0..3

    const size_t rowBase = (size_t)blockIdx.x * 64;
    const float* gA0 = adj + rowBase * N_NODES;

    float acc[2][4][4];
#pragma unroll
    for (int mt = 0; mt < 2; ++mt)
#pragma unroll
        for (int nt = 0; nt < 4; ++nt)
#pragma unroll
            for (int e = 0; e < 4; ++e) acc[mt][nt][e] = 0.f;

    const int NK = N_NODES / BK;        // 256

    auto issue = [&](int kt) {
        const int stage = kt % STAGES;
        float4* As4 = As4base + stage * A_STAGE_F4;
        float4* Hs4 = Hs4base + stage * H_STAGE_F4;
        const float* gA = gA0 + kt * BK;
#pragma unroll
        for (int i = 0; i < 4; ++i) {                 // 64x64 = 1024 float4
            int e   = i * 256 + tid;
            int row = e >> 4;
            int c4  = e & 15;
            cp_async16(&As4[row * 16 + (c4 ^ (row & 7))],
                       gA + (size_t)row * N_NODES + c4 * 4);
        }
        const float* gH = g_h + (size_t)kt * BK * OUT_F;
#pragma unroll
        for (int i = 0; i < 4; ++i) {                 // 64x64 = 1024 float4
            int e  = i * 256 + tid;
            int k  = e >> 4;
            int c4 = e & 15;
            cp_async16(&Hs4[k * 16 + (c4 ^ ((k & 3) << 1))],
                       gH + k * OUT_F + c4 * 4);
        }
    };

    issue(0); asm volatile("cp.async.commit_group;");
    issue(1); asm volatile("cp.async.commit_group;");

    for (int kt = 0; kt < NK; ++kt) {
        asm volatile("cp.async.wait_group 1;");
        __syncthreads();
        if (kt + 2 < NK) issue(kt + 2);
        asm volatile("cp.async.commit_group;");

        const int stage = kt % STAGES;
        const float*    As = (const float*)(As4base + stage * A_STAGE_F4);
        const uint32_t* Hs = (const uint32_t*)(Hs4base + stage * H_STAGE_F4);

#pragma unroll
        for (int ks = 0; ks < 4; ++ks) {
            const int kb = kh * 32 + ks * 8;
            const int k0 = kb + tig;
            const int k1 = k0 + 4;
            // A element (r,k) at word r*64 + (((k>>2)^(r&7))<<2) + (k&3), rna-rounded
            uint32_t afr[2][4];
#pragma unroll
            for (int mt = 0; mt < 2; ++mt) {
                int r = wm * 32 + mt * 16 + g;
                afr[mt][0] = f2tf32(As[r * 64       + (((k0 >> 2) ^ (r & 7)) << 2) + (k0 & 3)]);
                afr[mt][1] = f2tf32(As[(r + 8) * 64 + (((k0 >> 2) ^ (r & 7)) << 2) + (k0 & 3)]);
                afr[mt][2] = f2tf32(As[r * 64       + (((k1 >> 2) ^ (r & 7)) << 2) + (k1 & 3)]);
                afr[mt][3] = f2tf32(As[(r + 8) * 64 + (((k1 >> 2) ^ (r & 7)) << 2) + (k1 & 3)]);
            }
            // H element (k,n) at word k*64 + (n ^ ((k&3)<<3)); already tf32 bits: no cvt
            uint32_t bfr[4][2];
#pragma unroll
            for (int nt = 0; nt < 4; ++nt) {
                int n = wn * 32 + nt * 8 + g;
                bfr[nt][0] = Hs[k0 * 64 + (n ^ ((k0 & 3) << 3))];
                bfr[nt][1] = Hs[k1 * 64 + (n ^ ((k1 & 3) << 3))];
            }
#pragma unroll
            for (int mt = 0; mt < 2; ++mt)
#pragma unroll
                for (int nt = 0; nt < 4; ++nt)
                    MMA_TF32(acc[mt][nt], afr[mt], bfr[nt]);
        }
    }

    // ---- split-K reduction: warps 4-7 dump acc to smem, warps 0-3 add ----
    __syncthreads();                       // everyone done reading last stage
    float4* red = smem;                    // reuse pipeline smem (16KB used)
    const int wq = wid & 3;                // (wm, wn) pair id
    if (kh == 1) {
#pragma unroll
        for (int mt = 0; mt < 2; ++mt)
#pragma unroll
            for (int nt = 0; nt < 4; ++nt)
                red[((wq * 2 + mt) * 4 + nt) * 32 + lane] =
                    make_float4(acc[mt][nt][0], acc[mt][nt][1],
                                acc[mt][nt][2], acc[mt][nt][3]);
    }
    __syncthreads();
    if (kh == 0) {
#pragma unroll
        for (int mt = 0; mt < 2; ++mt) {
            size_t r = rowBase + wm * 32 + mt * 16 + g;
#pragma unroll
            for (int nt = 0; nt < 4; ++nt) {
                float4 o = red[((wq * 2 + mt) * 4 + nt) * 32 + lane];
                int c = wn * 32 + nt * 8 + tig * 2;
                float2 v0, v1;
                v0.x = fmaxf(acc[mt][nt][0] + o.x, 0.f);
                v0.y = fmaxf(acc[mt][nt][1] + o.y, 0.f);
                v1.x = fmaxf(acc[mt][nt][2] + o.z, 0.f);
                v1.y = fmaxf(acc[mt][nt][3] + o.w, 0.f);
                *(float2*)&out[r * OUT_F + c]       = v0;
                *(float2*)&out[(r + 8) * OUT_F + c] = v1;
            }
        }
    }
}

// ---------------------------------------------------------------------------
extern "C" void kernel_launch(void* const* d_in, const int* in_sizes, int n_in,
                              void* d_out, int out_size)
{
    const float* x   = (const float*)d_in[0];   // [16384, 256]
    const float* adj = (const float*)d_in[1];   // [16384, 16384]
    const float* W   = (const float*)d_in[2];   // [256, 64]
    const float* b   = (const float*)d_in[3];   // [64]
    float* out = (float*)d_out;                 // [16384, 64]

    cudaFuncSetAttribute(agg_kernel,
                         cudaFuncAttributeMaxDynamicSharedMemorySize, SMEM_BYTES);

    linear_kernel<<<N_NODES / 64, 128>>>(x, W, b);
    agg_kernel<<<N_NODES / 64, 256, SMEM_BYTES>>>(adj, out);
}

// round 13
// speedup vs baseline: 1.7764x; 1.1201x over previous
#include <cuda_runtime.h>
#include <cstdint>

#define N_NODES 16384
#define IN_F    256
#define OUT_F   64
#define KSPLIT  4
#define KRANGE  (N_NODES / KSPLIT)   // 4096

// h = x@W + b, pre-rounded to tf32 bit pattern: [16384][64] f32 = 4MB
__device__ float g_h[N_NODES * OUT_F];
// split-K partials: [KSPLIT][16384][64] f32 = 16MB
__device__ float g_part[KSPLIT * N_NODES * OUT_F];

__device__ __forceinline__ uint32_t f2tf32(float f) {
    uint32_t u;
    asm("cvt.rna.tf32.f32 %0, %1;" : "=r"(u) : "f"(f));
    return u;
}
__device__ __forceinline__ void cp_async16(void* sm, const void* gm) {
    uint32_t s = (uint32_t)__cvta_generic_to_shared(sm);
    asm volatile("cp.async.cg.shared.global [%0], [%1], 16;" :: "r"(s), "l"(gm));
}

#define MMA_TF32(d, a, bf)                                                    \
    asm volatile(                                                             \
        "mma.sync.aligned.m16n8k8.row.col.f32.tf32.tf32.f32 "                 \
        "{%0,%1,%2,%3}, {%4,%5,%6,%7}, {%8,%9}, {%0,%1,%2,%3};"               \
        : "+f"(d[0]), "+f"(d[1]), "+f"(d[2]), "+f"(d[3])                      \
        : "r"(a[0]), "r"(a[1]), "r"(a[2]), "r"(a[3]), "r"(bf[0]), "r"(bf[1]))

// ---------------------------------------------------------------------------
// Kernel A: g_h = tf32_round(x @ W + b)
// BM=64 rows/block (grid=256), 128 threads, 4x8 register tile, BK=32
// ---------------------------------------------------------------------------
__global__ __launch_bounds__(128) void linear_kernel(
    const float* __restrict__ x, const float* __restrict__ W,
    const float* __restrict__ b)
{
    __shared__ float xs_t[32][68];
    __shared__ float Ws[32][68];

    const int tid  = threadIdx.x;
    const int rb   = blockIdx.x * 64;
    const int trow = tid >> 3;
    const int tcol = tid & 7;
    const int r0   = trow * 4;
    const int c0   = tcol * 8;

    float acc[4][8];
#pragma unroll
    for (int i = 0; i < 4; ++i)
#pragma unroll
        for (int j = 0; j < 8; ++j) acc[i][j] = 0.f;

    for (int kt = 0; kt < IN_F / 32; ++kt) {
#pragma unroll
        for (int i = 0; i < 4; ++i) {
            int e = i * 128 + tid;
            int row = e >> 3;
            int c4  = e & 7;
            float4 v = *(const float4*)(x + (size_t)(rb + row) * IN_F + kt * 32 + c4 * 4);
            xs_t[c4 * 4 + 0][row] = v.x;
            xs_t[c4 * 4 + 1][row] = v.y;
            xs_t[c4 * 4 + 2][row] = v.z;
            xs_t[c4 * 4 + 3][row] = v.w;
        }
#pragma unroll
        for (int i = 0; i < 4; ++i) {
            int e = i * 128 + tid;
            int row = e >> 4;
            int c4  = e & 15;
            *(float4*)&Ws[row][c4 * 4] =
                *(const float4*)(W + (size_t)(kt * 32 + row) * OUT_F + c4 * 4);
        }
        __syncthreads();

#pragma unroll
        for (int k = 0; k < 32; ++k) {
            float4 xa = *(const float4*)&xs_t[k][r0];
            float4 wa = *(const float4*)&Ws[k][c0];
            float4 wb = *(const float4*)&Ws[k][c0 + 4];
            float xr[4] = {xa.x, xa.y, xa.z, xa.w};
            float wr[8] = {wa.x, wa.y, wa.z, wa.w, wb.x, wb.y, wb.z, wb.w};
#pragma unroll
            for (int i = 0; i < 4; ++i)
#pragma unroll
                for (int j = 0; j < 8; ++j) acc[i][j] += xr[i] * wr[j];
        }
        __syncthreads();
    }

    float bb[8];
#pragma unroll
    for (int j = 0; j < 8; ++j) bb[j] = b[c0 + j];

#pragma unroll
    for (int i = 0; i < 4; ++i) {
        float v[8];
#pragma unroll
        for (int j = 0; j < 8; ++j)
            v[j] = __uint_as_float(f2tf32(acc[i][j] + bb[j]));   // pre-round
        float* dst = g_h + (size_t)(rb + r0 + i) * OUT_F + c0;
        *(float4*)dst       = make_float4(v[0], v[1], v[2], v[3]);
        *(float4*)(dst + 4) = make_float4(v[4], v[5], v[6], v[7]);
    }
}

// ---------------------------------------------------------------------------
// Kernel B: g_part[kz] = adj[:, kz-slice] @ h[kz-slice]   (tf32 mma.sync)
// BM=64, BN=64, BK=32; grid (256, 4); 256 thr = 8 warps: 2M x 2N x 2K
// 4-stage cp.async pipeline, 64KB dynamic smem, 3 CTAs/SM
// ---------------------------------------------------------------------------
#define STAGES 4
#define BK     32
#define A_ST_F4 512                 // 64 x 32 f32 = 8KB
#define H_ST_F4 512                 // 32 x 64 f32 = 8KB
#define ST_F4   (A_ST_F4 + H_ST_F4)
#define SMEM_BYTES (STAGES * ST_F4 * 16)   // 65536

__global__ __launch_bounds__(256, 3) void agg_kernel(
    const float* __restrict__ adj)
{
    extern __shared__ float4 smem[];

    const int tid   = threadIdx.x;
    const int lane  = tid & 31;
    const int wid   = tid >> 5;
    const int wm    = wid & 1;          // M half (32 rows)
    const int wn    = (wid >> 1) & 1;   // N half (32 cols)
    const int kh    = wid >> 2;         // K half (16 k per iter)
    const int g     = lane >> 2;        // 0..7
    const int tig   = lane & 3;         // 0..3

    const int    kz      = blockIdx.y;
    const size_t rowBase = (size_t)blockIdx.x * 64;
    const float* gA0 = adj + rowBase * N_NODES + (size_t)kz * KRANGE;
    const float* gH0 = g_h + (size_t)kz * KRANGE * OUT_F;

    float acc[2][4][4];
#pragma unroll
    for (int mt = 0; mt < 2; ++mt)
#pragma unroll
        for (int nt = 0; nt < 4; ++nt)
#pragma unroll
            for (int e = 0; e < 4; ++e) acc[mt][nt][e] = 0.f;

    const int NK = KRANGE / BK;         // 128

    auto issue = [&](int kt) {
        const int st = kt & (STAGES - 1);
        float4* As4 = smem + st * ST_F4;             // [64][8]  swizzled
        float4* Hs4 = As4 + A_ST_F4;                 // [32][16] swizzled
        const float* gA = gA0 + kt * BK;
#pragma unroll
        for (int i = 0; i < 2; ++i) {                // 64x32 = 512 float4
            int e   = i * 256 + tid;
            int row = e >> 3;
            int c4  = e & 7;
            cp_async16(&As4[row * 8 + (c4 ^ (row & 7))],
                       gA + (size_t)row * N_NODES + c4 * 4);
        }
        const float* gH = gH0 + (size_t)kt * BK * OUT_F;
#pragma unroll
        for (int i = 0; i < 2; ++i) {                // 32x64 = 512 float4
            int e  = i * 256 + tid;
            int k  = e >> 4;
            int c4 = e & 15;
            cp_async16(&Hs4[k * 16 + (c4 ^ ((k & 3) << 1))],
                       gH + k * OUT_F + c4 * 4);
        }
    };

    issue(0); asm volatile("cp.async.commit_group;");
    issue(1); asm volatile("cp.async.commit_group;");
    issue(2); asm volatile("cp.async.commit_group;");

    for (int kt = 0; kt < NK; ++kt) {
        asm volatile("cp.async.wait_group 2;");
        __syncthreads();
        if (kt + 3 < NK) issue(kt + 3);
        asm volatile("cp.async.commit_group;");      // uniform group count

        const int st = kt & (STAGES - 1);
        const float*    As = (const float*)(smem + st * ST_F4);
        const uint32_t* Hs = (const uint32_t*)(smem + st * ST_F4 + A_ST_F4);

#pragma unroll
        for (int ks = 0; ks < 2; ++ks) {
            const int k0 = kh * 16 + ks * 8 + tig;
            const int k1 = k0 + 4;
            // A element (r,k) at word r*32 + (((k>>2)^(r&7))<<2) + (k&3)
            uint32_t afr[2][4];
#pragma unroll
            for (int mt = 0; mt < 2; ++mt) {
                int r = wm * 32 + mt * 16 + g;
                afr[mt][0] = f2tf32(As[r * 32       + (((k0 >> 2) ^ (r & 7)) << 2) + (k0 & 3)]);
                afr[mt][1] = f2tf32(As[(r + 8) * 32 + (((k0 >> 2) ^ (r & 7)) << 2) + (k0 & 3)]);
                afr[mt][2] = f2tf32(As[r * 32       + (((k1 >> 2) ^ (r & 7)) << 2) + (k1 & 3)]);
                afr[mt][3] = f2tf32(As[(r + 8) * 32 + (((k1 >> 2) ^ (r & 7)) << 2) + (k1 & 3)]);
            }
            // H element (k,n) at word k*64 + (n ^ ((k&3)<<3)); pre-rounded: no cvt
            uint32_t bfr[4][2];
#pragma unroll
            for (int nt = 0; nt < 4; ++nt) {
                int n = wn * 32 + nt * 8 + g;
                bfr[nt][0] = Hs[k0 * 64 + (n ^ ((k0 & 3) << 3))];
                bfr[nt][1] = Hs[k1 * 64 + (n ^ ((k1 & 3) << 3))];
            }
#pragma unroll
            for (int mt = 0; mt < 2; ++mt)
#pragma unroll
                for (int nt = 0; nt < 4; ++nt)
                    MMA_TF32(acc[mt][nt], afr[mt], bfr[nt]);
        }
    }

    // ---- in-CTA split-K (kh) reduction via smem, then write partial ----
    __syncthreads();
    float4* red = smem;                    // 16KB of stage-0 region
    const int wq = wid & 3;                // (wm, wn) pair id
    if (kh == 1) {
#pragma unroll
        for (int mt = 0; mt < 2; ++mt)
#pragma unroll
            for (int nt = 0; nt < 4; ++nt)
                red[((wq * 2 + mt) * 4 + nt) * 32 + lane] =
                    make_float4(acc[mt][nt][0], acc[mt][nt][1],
                                acc[mt][nt][2], acc[mt][nt][3]);
    }
    __syncthreads();
    if (kh == 0) {
        float* part = g_part + (size_t)kz * N_NODES * OUT_F;
#pragma unroll
        for (int mt = 0; mt < 2; ++mt) {
            size_t r = rowBase + wm * 32 + mt * 16 + g;
#pragma unroll
            for (int nt = 0; nt < 4; ++nt) {
                float4 o = red[((wq * 2 + mt) * 4 + nt) * 32 + lane];
                int c = wn * 32 + nt * 8 + tig * 2;
                float2 v0, v1;
                v0.x = acc[mt][nt][0] + o.x;
                v0.y = acc[mt][nt][1] + o.y;
                v1.x = acc[mt][nt][2] + o.z;
                v1.y = acc[mt][nt][3] + o.w;
                *(float2*)&part[r * OUT_F + c]       = v0;
                *(float2*)&part[(r + 8) * OUT_F + c] = v1;
            }
        }
    }
}

// ---------------------------------------------------------------------------
// Kernel C: out = relu(sum_kz g_part[kz])   (1M floats, float4 per thread)
// ---------------------------------------------------------------------------
__global__ __launch_bounds__(256) void reduce_kernel(float* __restrict__ out)
{
    const int S = N_NODES * OUT_F / 4;     // 262144 float4
    int i = blockIdx.x * 256 + threadIdx.x;
    const float4* p = (const float4*)g_part;
    float4 a = p[i];
    float4 b = p[i + S];
    float4 c = p[i + 2 * S];
    float4 d = p[i + 3 * S];
    float4 v;
    v.x = fmaxf(a.x + b.x + c.x + d.x, 0.f);
    v.y = fmaxf(a.y + b.y + c.y + d.y, 0.f);
    v.z = fmaxf(a.z + b.z + c.z + d.z, 0.f);
    v.w = fmaxf(a.w + b.w + c.w + d.w, 0.f);
    ((float4*)out)[i] = v;
}

// ---------------------------------------------------------------------------
extern "C" void kernel_launch(void* const* d_in, const int* in_sizes, int n_in,
                              void* d_out, int out_size)
{
    const float* x   = (const float*)d_in[0];   // [16384, 256]
    const float* adj = (const float*)d_in[1];   // [16384, 16384]
    const float* W   = (const float*)d_in[2];   // [256, 64]
    const float* b   = (const float*)d_in[3];   // [64]
    float* out = (float*)d_out;                 // [16384, 64]

    cudaFuncSetAttribute(agg_kernel,
                         cudaFuncAttributeMaxDynamicSharedMemorySize, SMEM_BYTES);

    linear_kernel<<<N_NODES / 64, 128>>>(x, W, b);
    dim3 grid(N_NODES / 64, KSPLIT);
    agg_kernel<<<grid, 256, SMEM_BYTES>>>(adj);
    reduce_kernel<<<N_NODES * OUT_F / 4 / 256, 256>>>(out);
}

// round 14
// speedup vs baseline: 1.7795x; 1.0018x over previous
#include <cuda_runtime.h>
#include <cstdint>

#define N_NODES 16384
#define IN_F    256
#define OUT_F   64
#define KSPLIT  8
#define KRANGE  (N_NODES / KSPLIT)   // 2048

// h = x@W + b, pre-rounded to tf32 bit pattern: [16384][64] f32 = 4MB
__device__ float g_h[N_NODES * OUT_F];
// split-K partials: [KSPLIT][16384][64] f32 = 32MB
__device__ float g_part[KSPLIT * N_NODES * OUT_F];

__device__ __forceinline__ uint32_t f2tf32(float f) {
    uint32_t u;
    asm("cvt.rna.tf32.f32 %0, %1;" : "=r"(u) : "f"(f));
    return u;
}
__device__ __forceinline__ void cp_async16(void* sm, const void* gm) {
    uint32_t s = (uint32_t)__cvta_generic_to_shared(sm);
    asm volatile("cp.async.cg.shared.global [%0], [%1], 16;" :: "r"(s), "l"(gm));
}

#define MMA_TF32(d, a, bf)                                                    \
    asm volatile(                                                             \
        "mma.sync.aligned.m16n8k8.row.col.f32.tf32.tf32.f32 "                 \
        "{%0,%1,%2,%3}, {%4,%5,%6,%7}, {%8,%9}, {%0,%1,%2,%3};"               \
        : "+f"(d[0]), "+f"(d[1]), "+f"(d[2]), "+f"(d[3])                      \
        : "r"(a[0]), "r"(a[1]), "r"(a[2]), "r"(a[3]), "r"(bf[0]), "r"(bf[1]))

// ---------------------------------------------------------------------------
// Kernel A: g_h = tf32_round(x @ W + b)
// BM=64 rows/block (grid=256), 256 threads (8 warps), 2x8 tile, BK=32
// ---------------------------------------------------------------------------
__global__ __launch_bounds__(256) void linear_kernel(
    const float* __restrict__ x, const float* __restrict__ W,
    const float* __restrict__ b)
{
    __shared__ float xs_t[32][68];
    __shared__ float Ws[32][68];

    const int tid  = threadIdx.x;
    const int rb   = blockIdx.x * 64;
    const int trow = tid >> 3;        // 0..31
    const int tcol = tid & 7;         // 0..7
    const int r0   = trow * 2;
    const int c0   = tcol * 8;

    float acc[2][8];
#pragma unroll
    for (int i = 0; i < 2; ++i)
#pragma unroll
        for (int j = 0; j < 8; ++j) acc[i][j] = 0.f;

    for (int kt = 0; kt < IN_F / 32; ++kt) {
        // x tile 64x32, transposed into smem
#pragma unroll
        for (int i = 0; i < 2; ++i) {
            int e = i * 256 + tid;
            int row = e >> 3;
            int c4  = e & 7;
            float4 v = *(const float4*)(x + (size_t)(rb + row) * IN_F + kt * 32 + c4 * 4);
            xs_t[c4 * 4 + 0][row] = v.x;
            xs_t[c4 * 4 + 1][row] = v.y;
            xs_t[c4 * 4 + 2][row] = v.z;
            xs_t[c4 * 4 + 3][row] = v.w;
        }
        // W tile 32x64
#pragma unroll
        for (int i = 0; i < 2; ++i) {
            int e = i * 256 + tid;
            int row = e >> 4;
            int c4  = e & 15;
            *(float4*)&Ws[row][c4 * 4] =
                *(const float4*)(W + (size_t)(kt * 32 + row) * OUT_F + c4 * 4);
        }
        __syncthreads();

#pragma unroll
        for (int k = 0; k < 32; ++k) {
            float2 xa = *(const float2*)&xs_t[k][r0];
            float4 wa = *(const float4*)&Ws[k][c0];
            float4 wb = *(const float4*)&Ws[k][c0 + 4];
            float xr[2] = {xa.x, xa.y};
            float wr[8] = {wa.x, wa.y, wa.z, wa.w, wb.x, wb.y, wb.z, wb.w};
#pragma unroll
            for (int i = 0; i < 2; ++i)
#pragma unroll
                for (int j = 0; j < 8; ++j) acc[i][j] += xr[i] * wr[j];
        }
        __syncthreads();
    }

    float bb[8];
#pragma unroll
    for (int j = 0; j < 8; ++j) bb[j] = b[c0 + j];

#pragma unroll
    for (int i = 0; i < 2; ++i) {
        float v[8];
#pragma unroll
        for (int j = 0; j < 8; ++j)
            v[j] = __uint_as_float(f2tf32(acc[i][j] + bb[j]));   // rna pre-round
        float* dst = g_h + (size_t)(rb + r0 + i) * OUT_F + c0;
        *(float4*)dst       = make_float4(v[0], v[1], v[2], v[3]);
        *(float4*)(dst + 4) = make_float4(v[4], v[5], v[6], v[7]);
    }
}

// ---------------------------------------------------------------------------
// Kernel B: g_part[kz] = adj[:, kz-slice] @ h[kz-slice]   (tf32 mma.sync)
// BM=64, BN=64, BK=32; grid (256, 8); 256 thr = 8 warps: 2M x 2N x 2K
// 4-stage cp.async pipeline, 64KB dynamic smem, 3 CTAs/SM
// A operand: raw f32 bits -> HW tf32 truncation (no cvt); H pre-rounded rna
// ---------------------------------------------------------------------------
#define STAGES 4
#define BK     32
#define A_ST_F4 512                 // 64 x 32 f32 = 8KB
#define H_ST_F4 512                 // 32 x 64 f32 = 8KB
#define ST_F4   (A_ST_F4 + H_ST_F4)
#define SMEM_BYTES (STAGES * ST_F4 * 16)   // 65536

__global__ __launch_bounds__(256, 3) void agg_kernel(
    const float* __restrict__ adj)
{
    extern __shared__ float4 smem[];

    const int tid   = threadIdx.x;
    const int lane  = tid & 31;
    const int wid   = tid >> 5;
    const int wm    = wid & 1;          // M half (32 rows)
    const int wn    = (wid >> 1) & 1;   // N half (32 cols)
    const int kh    = wid >> 2;         // K half (16 k per iter)
    const int g     = lane >> 2;        // 0..7
    const int tig   = lane & 3;         // 0..3

    const int    kz      = blockIdx.y;
    const size_t rowBase = (size_t)blockIdx.x * 64;
    const float* gA0 = adj + rowBase * N_NODES + (size_t)kz * KRANGE;
    const float* gH0 = g_h + (size_t)kz * KRANGE * OUT_F;

    float acc[2][4][4];
#pragma unroll
    for (int mt = 0; mt < 2; ++mt)
#pragma unroll
        for (int nt = 0; nt < 4; ++nt)
#pragma unroll
            for (int e = 0; e < 4; ++e) acc[mt][nt][e] = 0.f;

    const int NK = KRANGE / BK;         // 64

    auto issue = [&](int kt) {
        const int st = kt & (STAGES - 1);
        float4* As4 = smem + st * ST_F4;             // [64][8]  swizzled
        float4* Hs4 = As4 + A_ST_F4;                 // [32][16] swizzled
        const float* gA = gA0 + kt * BK;
#pragma unroll
        for (int i = 0; i < 2; ++i) {                // 64x32 = 512 float4
            int e   = i * 256 + tid;
            int row = e >> 3;
            int c4  = e & 7;
            cp_async16(&As4[row * 8 + (c4 ^ (row & 7))],
                       gA + (size_t)row * N_NODES + c4 * 4);
        }
        const float* gH = gH0 + (size_t)kt * BK * OUT_F;
#pragma unroll
        for (int i = 0; i < 2; ++i) {                // 32x64 = 512 float4
            int e  = i * 256 + tid;
            int k  = e >> 4;
            int c4 = e & 15;
            cp_async16(&Hs4[k * 16 + (c4 ^ ((k & 3) << 1))],
                       gH + k * OUT_F + c4 * 4);
        }
    };

    issue(0); asm volatile("cp.async.commit_group;");
    issue(1); asm volatile("cp.async.commit_group;");
    issue(2); asm volatile("cp.async.commit_group;");

    for (int kt = 0; kt < NK; ++kt) {
        asm volatile("cp.async.wait_group 2;");
        __syncthreads();
        if (kt + 3 < NK) issue(kt + 3);
        asm volatile("cp.async.commit_group;");      // uniform group count

        const int st = kt & (STAGES - 1);
        const uint32_t* As = (const uint32_t*)(smem + st * ST_F4);
        const uint32_t* Hs = (const uint32_t*)(smem + st * ST_F4 + A_ST_F4);

#pragma unroll
        for (int ks = 0; ks < 2; ++ks) {
            const int k0 = kh * 16 + ks * 8 + tig;
            const int k1 = k0 + 4;
            // A element (r,k) at word r*32 + (((k>>2)^(r&7))<<2) + (k&3)
            // raw f32 bits: HW tf32 path uses upper 19 bits (truncation)
            uint32_t afr[2][4];
#pragma unroll
            for (int mt = 0; mt < 2; ++mt) {
                int r = wm * 32 + mt * 16 + g;
                afr[mt][0] = As[r * 32       + (((k0 >> 2) ^ (r & 7)) << 2) + (k0 & 3)];
                afr[mt][1] = As[(r + 8) * 32 + (((k0 >> 2) ^ (r & 7)) << 2) + (k0 & 3)];
                afr[mt][2] = As[r * 32       + (((k1 >> 2) ^ (r & 7)) << 2) + (k1 & 3)];
                afr[mt][3] = As[(r + 8) * 32 + (((k1 >> 2) ^ (r & 7)) << 2) + (k1 & 3)];
            }
            // H element (k,n) at word k*64 + (n ^ ((k&3)<<3)); pre-rounded rna
            uint32_t bfr[4][2];
#pragma unroll
            for (int nt = 0; nt < 4; ++nt) {
                int n = wn * 32 + nt * 8 + g;
                bfr[nt][0] = Hs[k0 * 64 + (n ^ ((k0 & 3) << 3))];
                bfr[nt][1] = Hs[k1 * 64 + (n ^ ((k1 & 3) << 3))];
            }
#pragma unroll
            for (int mt = 0; mt < 2; ++mt)
#pragma unroll
                for (int nt = 0; nt < 4; ++nt)
                    MMA_TF32(acc[mt][nt], afr[mt], bfr[nt]);
        }
    }

    // ---- in-CTA split-K (kh) reduction via smem, then write partial ----
    __syncthreads();
    float4* red = smem;                    // 16KB of stage-0 region
    const int wq = wid & 3;                // (wm, wn) pair id
    if (kh == 1) {
#pragma unroll
        for (int mt = 0; mt < 2; ++mt)
#pragma unroll
            for (int nt = 0; nt < 4; ++nt)
                red[((wq * 2 + mt) * 4 + nt) * 32 + lane] =
                    make_float4(acc[mt][nt][0], acc[mt][nt][1],
                                acc[mt][nt][2], acc[mt][nt][3]);
    }
    __syncthreads();
    if (kh == 0) {
        float* part = g_part + (size_t)kz * N_NODES * OUT_F;
#pragma unroll
        for (int mt = 0; mt < 2; ++mt) {
            size_t r = rowBase + wm * 32 + mt * 16 + g;
#pragma unroll
            for (int nt = 0; nt < 4; ++nt) {
                float4 o = red[((wq * 2 + mt) * 4 + nt) * 32 + lane];
                int c = wn * 32 + nt * 8 + tig * 2;
                float2 v0, v1;
                v0.x = acc[mt][nt][0] + o.x;
                v0.y = acc[mt][nt][1] + o.y;
                v1.x = acc[mt][nt][2] + o.z;
                v1.y = acc[mt][nt][3] + o.w;
                *(float2*)&part[r * OUT_F + c]       = v0;
                *(float2*)&part[(r + 8) * OUT_F + c] = v1;
            }
        }
    }
}

// ---------------------------------------------------------------------------
// Kernel C: out = relu(sum_kz g_part[kz])
// ---------------------------------------------------------------------------
__global__ __launch_bounds__(256) void reduce_kernel(float* __restrict__ out)
{
    const int S = N_NODES * OUT_F / 4;     // 262144 float4
    int i = blockIdx.x * 256 + threadIdx.x;
    const float4* p = (const float4*)g_part;
    float4 v = p[i];
#pragma unroll
    for (int z = 1; z < KSPLIT; ++z) {
        float4 t = p[i + z * S];
        v.x += t.x; v.y += t.y; v.z += t.z; v.w += t.w;
    }
    v.x = fmaxf(v.x, 0.f);
    v.y = fmaxf(v.y, 0.f);
    v.z = fmaxf(v.z, 0.f);
    v.w = fmaxf(v.w, 0.f);
    ((float4*)out)[i] = v;
}

// ---------------------------------------------------------------------------
extern "C" void kernel_launch(void* const* d_in, const int* in_sizes, int n_in,
                              void* d_out, int out_size)
{
    const float* x   = (const float*)d_in[0];   // [16384, 256]
    const float* adj = (const float*)d_in[1];   // [16384, 16384]
    const float* W   = (const float*)d_in[2];   // [256, 64]
    const float* b   = (const float*)d_in[3];   // [64]
    float* out = (float*)d_out;                 // [16384, 64]

    cudaFuncSetAttribute(agg_kernel,
                         cudaFuncAttributeMaxDynamicSharedMemorySize, SMEM_BYTES);

    linear_kernel<<<N_NODES / 64, 256>>>(x, W, b);
    dim3 grid(N_NODES / 64, KSPLIT);
    agg_kernel<<<grid, 256, SMEM_BYTES>>>(adj);
    reduce_kernel<<<N_NODES * OUT_F / 4 / 256, 256>>>(out);
}

// round 15
// speedup vs baseline: 2.1076x; 1.1843x over previous
#include <cuda_runtime.h>
#include <cstdint>

#define N_NODES 16384
#define IN_F    256
#define OUT_F   64
#define KSPLIT  8
#define KRANGE  (N_NODES / KSPLIT)   // 2048

// h = x@W + b, pre-rounded to tf32 bit pattern: [16384][64] f32 = 4MB
__device__ float g_h[N_NODES * OUT_F];
// split-K partials: [KSPLIT][16384][64] f32 = 32MB
__device__ float g_part[KSPLIT * N_NODES * OUT_F];

__device__ __forceinline__ uint32_t f2tf32(float f) {
    uint32_t u;
    asm("cvt.rna.tf32.f32 %0, %1;" : "=r"(u) : "f"(f));
    return u;
}
__device__ __forceinline__ void cp_async16(void* sm, const void* gm) {
    uint32_t s = (uint32_t)__cvta_generic_to_shared(sm);
    asm volatile("cp.async.cg.shared.global [%0], [%1], 16;" :: "r"(s), "l"(gm));
}

#define MMA_TF32(d, a, bf)                                                    \
    asm volatile(                                                             \
        "mma.sync.aligned.m16n8k8.row.col.f32.tf32.tf32.f32 "                 \
        "{%0,%1,%2,%3}, {%4,%5,%6,%7}, {%8,%9}, {%0,%1,%2,%3};"               \
        : "+f"(d[0]), "+f"(d[1]), "+f"(d[2]), "+f"(d[3])                      \
        : "r"(a[0]), "r"(a[1]), "r"(a[2]), "r"(a[3]), "r"(bf[0]), "r"(bf[1]))

// ---------------------------------------------------------------------------
// Kernel A: g_h = rna(x @ W + b)  via tf32 mma.sync (rna on both operands)
// BM=64 (grid 256), 256 thr = 8 warps: 2M x 2N x 2K-half; BK=32, NK=8
// ---------------------------------------------------------------------------
#define L_STAGES 4
#define L_A_F4   512                // 64 x 32 f32 = 8KB
#define L_H_F4   512                // 32 x 64 f32 = 8KB
#define L_ST_F4  (L_A_F4 + L_H_F4)
#define L_SMEM   (L_STAGES * L_ST_F4 * 16)   // 65536

__global__ __launch_bounds__(256) void linear_kernel(
    const float* __restrict__ x, const float* __restrict__ W,
    const float* __restrict__ b)
{
    extern __shared__ float4 smem[];

    const int tid  = threadIdx.x;
    const int lane = tid & 31;
    const int wid  = tid >> 5;
    const int wm   = wid & 1;
    const int wn   = (wid >> 1) & 1;
    const int kh   = wid >> 2;
    const int g    = lane >> 2;
    const int tig  = lane & 3;

    const size_t rowBase = (size_t)blockIdx.x * 64;
    const float* gA0 = x + rowBase * IN_F;

    float acc[2][4][4];
#pragma unroll
    for (int mt = 0; mt < 2; ++mt)
#pragma unroll
        for (int nt = 0; nt < 4; ++nt)
#pragma unroll
            for (int e = 0; e < 4; ++e) acc[mt][nt][e] = 0.f;

    const int NK = IN_F / 32;       // 8

    auto issue = [&](int kt) {
        const int st = kt & (L_STAGES - 1);
        float4* As4 = smem + st * L_ST_F4;
        float4* Hs4 = As4 + L_A_F4;
        const float* gA = gA0 + kt * 32;
#pragma unroll
        for (int i = 0; i < 2; ++i) {
            int e   = i * 256 + tid;
            int row = e >> 3;
            int c4  = e & 7;
            cp_async16(&As4[row * 8 + (c4 ^ (row & 7))],
                       gA + (size_t)row * IN_F + c4 * 4);
        }
        const float* gW = W + (size_t)kt * 32 * OUT_F;
#pragma unroll
        for (int i = 0; i < 2; ++i) {
            int e  = i * 256 + tid;
            int k  = e >> 4;
            int c4 = e & 15;
            cp_async16(&Hs4[k * 16 + (c4 ^ ((k & 3) << 1))],
                       gW + k * OUT_F + c4 * 4);
        }
    };

    issue(0); asm volatile("cp.async.commit_group;");
    issue(1); asm volatile("cp.async.commit_group;");
    issue(2); asm volatile("cp.async.commit_group;");

    for (int kt = 0; kt < NK; ++kt) {
        asm volatile("cp.async.wait_group 2;");
        __syncthreads();
        if (kt + 3 < NK) issue(kt + 3);
        asm volatile("cp.async.commit_group;");

        const int st = kt & (L_STAGES - 1);
        const float* As = (const float*)(smem + st * L_ST_F4);
        const float* Hs = (const float*)(smem + st * L_ST_F4 + L_A_F4);

#pragma unroll
        for (int ks = 0; ks < 2; ++ks) {
            const int k0 = kh * 16 + ks * 8 + tig;
            const int k1 = k0 + 4;
            uint32_t afr[2][4];
#pragma unroll
            for (int mt = 0; mt < 2; ++mt) {
                int r = wm * 32 + mt * 16 + g;
                afr[mt][0] = f2tf32(As[r * 32       + (((k0 >> 2) ^ (r & 7)) << 2) + (k0 & 3)]);
                afr[mt][1] = f2tf32(As[(r + 8) * 32 + (((k0 >> 2) ^ (r & 7)) << 2) + (k0 & 3)]);
                afr[mt][2] = f2tf32(As[r * 32       + (((k1 >> 2) ^ (r & 7)) << 2) + (k1 & 3)]);
                afr[mt][3] = f2tf32(As[(r + 8) * 32 + (((k1 >> 2) ^ (r & 7)) << 2) + (k1 & 3)]);
            }
            uint32_t bfr[4][2];
#pragma unroll
            for (int nt = 0; nt < 4; ++nt) {
                int n = wn * 32 + nt * 8 + g;
                bfr[nt][0] = f2tf32(Hs[k0 * 64 + (n ^ ((k0 & 3) << 3))]);
                bfr[nt][1] = f2tf32(Hs[k1 * 64 + (n ^ ((k1 & 3) << 3))]);
            }
#pragma unroll
            for (int mt = 0; mt < 2; ++mt)
#pragma unroll
                for (int nt = 0; nt < 4; ++nt)
                    MMA_TF32(acc[mt][nt], afr[mt], bfr[nt]);
        }
    }

    // split-K(kh) reduce + bias + rna-round + store h
    __syncthreads();
    float4* red = smem;
    const int wq = wid & 3;
    if (kh == 1) {
#pragma unroll
        for (int mt = 0; mt < 2; ++mt)
#pragma unroll
            for (int nt = 0; nt < 4; ++nt)
                red[((wq * 2 + mt) * 4 + nt) * 32 + lane] =
                    make_float4(acc[mt][nt][0], acc[mt][nt][1],
                                acc[mt][nt][2], acc[mt][nt][3]);
    }
    __syncthreads();
    if (kh == 0) {
#pragma unroll
        for (int mt = 0; mt < 2; ++mt) {
            size_t r = rowBase + wm * 32 + mt * 16 + g;
#pragma unroll
            for (int nt = 0; nt < 4; ++nt) {
                float4 o = red[((wq * 2 + mt) * 4 + nt) * 32 + lane];
                int c = wn * 32 + nt * 8 + tig * 2;
                float b0 = b[c], b1 = b[c + 1];
                float2 v0, v1;
                v0.x = __uint_as_float(f2tf32(acc[mt][nt][0] + o.x + b0));
                v0.y = __uint_as_float(f2tf32(acc[mt][nt][1] + o.y + b1));
                v1.x = __uint_as_float(f2tf32(acc[mt][nt][2] + o.z + b0));
                v1.y = __uint_as_float(f2tf32(acc[mt][nt][3] + o.w + b1));
                *(float2*)&g_h[r * OUT_F + c]       = v0;
                *(float2*)&g_h[(r + 8) * OUT_F + c] = v1;
            }
        }
    }
}

// ---------------------------------------------------------------------------
// Kernel B: g_part[kz] = adj[:, kz-slice] @ h[kz-slice]   (tf32 mma.sync)
// BM=128, BN=64, BK=32; grid (128, 8); 8 warps = 4M x 2N, warp tile 32x32
// 4-stage cp.async pipeline, 96KB dynamic smem, 2 CTAs/SM
// A: raw f32 bits (HW tf32 trunc); H pre-rounded rna
// ---------------------------------------------------------------------------
#define STAGES 4
#define BK     32
#define A_ST_F4 1024                // 128 x 32 f32 = 16KB
#define H_ST_F4 512                 // 32 x 64 f32 = 8KB
#define ST_F4   (A_ST_F4 + H_ST_F4)
#define SMEM_BYTES (STAGES * ST_F4 * 16)   // 98304

__global__ __launch_bounds__(256, 2) void agg_kernel(
    const float* __restrict__ adj)
{
    extern __shared__ float4 smem[];

    const int tid   = threadIdx.x;
    const int lane  = tid & 31;
    const int wid   = tid >> 5;
    const int warpM = wid & 3;          // 4 M quarters (32 rows each)
    const int warpN = wid >> 2;         // 2 N halves (32 cols each)
    const int g     = lane >> 2;
    const int tig   = lane & 3;

    const int    kz      = blockIdx.y;
    const size_t rowBase = (size_t)blockIdx.x * 128;
    const float* gA0 = adj + rowBase * N_NODES + (size_t)kz * KRANGE;
    const float* gH0 = g_h + (size_t)kz * KRANGE * OUT_F;

    float acc[2][4][4];
#pragma unroll
    for (int mt = 0; mt < 2; ++mt)
#pragma unroll
        for (int nt = 0; nt < 4; ++nt)
#pragma unroll
            for (int e = 0; e < 4; ++e) acc[mt][nt][e] = 0.f;

    const int NK = KRANGE / BK;         // 64

    auto issue = [&](int kt) {
        const int st = kt & (STAGES - 1);
        float4* As4 = smem + st * ST_F4;             // [128][8]  swizzled
        float4* Hs4 = As4 + A_ST_F4;                 // [32][16]  swizzled
        const float* gA = gA0 + kt * BK;
#pragma unroll
        for (int i = 0; i < 4; ++i) {                // 128x32 = 1024 float4
            int e   = i * 256 + tid;
            int row = e >> 3;
            int c4  = e & 7;
            cp_async16(&As4[row * 8 + (c4 ^ (row & 7))],
                       gA + (size_t)row * N_NODES + c4 * 4);
        }
        const float* gH = gH0 + (size_t)kt * BK * OUT_F;
#pragma unroll
        for (int i = 0; i < 2; ++i) {                // 32x64 = 512 float4
            int e  = i * 256 + tid;
            int k  = e >> 4;
            int c4 = e & 15;
            cp_async16(&Hs4[k * 16 + (c4 ^ ((k & 3) << 1))],
                       gH + k * OUT_F + c4 * 4);
        }
    };

    issue(0); asm volatile("cp.async.commit_group;");
    issue(1); asm volatile("cp.async.commit_group;");
    issue(2); asm volatile("cp.async.commit_group;");

    for (int kt = 0; kt < NK; ++kt) {
        asm volatile("cp.async.wait_group 2;");
        __syncthreads();
        if (kt + 3 < NK) issue(kt + 3);
        asm volatile("cp.async.commit_group;");      // uniform group count

        const int st = kt & (STAGES - 1);
        const uint32_t* As = (const uint32_t*)(smem + st * ST_F4);
        const uint32_t* Hs = (const uint32_t*)(smem + st * ST_F4 + A_ST_F4);

#pragma unroll
        for (int ks = 0; ks < 4; ++ks) {
            const int k0 = ks * 8 + tig;
            const int k1 = k0 + 4;
            // A element (r,k) at word r*32 + (((k>>2)^(r&7))<<2) + (k&3)
            uint32_t afr[2][4];
#pragma unroll
            for (int mt = 0; mt < 2; ++mt) {
                int r = warpM * 32 + mt * 16 + g;
                afr[mt][0] = As[r * 32       + (((k0 >> 2) ^ (r & 7)) << 2) + (k0 & 3)];
                afr[mt][1] = As[(r + 8) * 32 + (((k0 >> 2) ^ (r & 7)) << 2) + (k0 & 3)];
                afr[mt][2] = As[r * 32       + (((k1 >> 2) ^ (r & 7)) << 2) + (k1 & 3)];
                afr[mt][3] = As[(r + 8) * 32 + (((k1 >> 2) ^ (r & 7)) << 2) + (k1 & 3)];
            }
            // H element (k,n) at word k*64 + (n ^ ((k&3)<<3)); pre-rounded rna
            uint32_t bfr[4][2];
#pragma unroll
            for (int nt = 0; nt < 4; ++nt) {
                int n = warpN * 32 + nt * 8 + g;
                bfr[nt][0] = Hs[k0 * 64 + (n ^ ((k0 & 3) << 3))];
                bfr[nt][1] = Hs[k1 * 64 + (n ^ ((k1 & 3) << 3))];
            }
#pragma unroll
            for (int mt = 0; mt < 2; ++mt)
#pragma unroll
                for (int nt = 0; nt < 4; ++nt)
                    MMA_TF32(acc[mt][nt], afr[mt], bfr[nt]);
        }
    }

    // direct partial store (no in-CTA split-K)
    float* part = g_part + (size_t)kz * N_NODES * OUT_F;
#pragma unroll
    for (int mt = 0; mt < 2; ++mt) {
        size_t r = rowBase + warpM * 32 + mt * 16 + g;
#pragma unroll
        for (int nt = 0; nt < 4; ++nt) {
            int c = warpN * 32 + nt * 8 + tig * 2;
            float2 v0, v1;
            v0.x = acc[mt][nt][0];
            v0.y = acc[mt][nt][1];
            v1.x = acc[mt][nt][2];
            v1.y = acc[mt][nt][3];
            *(float2*)&part[r * OUT_F + c]       = v0;
            *(float2*)&part[(r + 8) * OUT_F + c] = v1;
        }
    }
}

// ---------------------------------------------------------------------------
// Kernel C: out = relu(sum_kz g_part[kz])
// ---------------------------------------------------------------------------
__global__ __launch_bounds__(256) void reduce_kernel(float* __restrict__ out)
{
    const int S = N_NODES * OUT_F / 4;     // 262144 float4
    int i = blockIdx.x * 256 + threadIdx.x;
    const float4* p = (const float4*)g_part;
    float4 v = p[i];
#pragma unroll
    for (int z = 1; z < KSPLIT; ++z) {
        float4 t = p[i + z * S];
        v.x += t.x; v.y += t.y; v.z += t.z; v.w += t.w;
    }
    v.x = fmaxf(v.x, 0.f);
    v.y = fmaxf(v.y, 0.f);
    v.z = fmaxf(v.z, 0.f);
    v.w = fmaxf(v.w, 0.f);
    ((float4*)out)[i] = v;
}

// ---------------------------------------------------------------------------
extern "C" void kernel_launch(void* const* d_in, const int* in_sizes, int n_in,
                              void* d_out, int out_size)
{
    const float* x   = (const float*)d_in[0];   // [16384, 256]
    const float* adj = (const float*)d_in[1];   // [16384, 16384]
    const float* W   = (const float*)d_in[2];   // [256, 64]
    const float* b   = (const float*)d_in[3];   // [64]
    float* out = (float*)d_out;                 // [16384, 64]

    cudaFuncSetAttribute(linear_kernel,
                         cudaFuncAttributeMaxDynamicSharedMemorySize, L_SMEM);
    cudaFuncSetAttribute(agg_kernel,
                         cudaFuncAttributeMaxDynamicSharedMemorySize, SMEM_BYTES);

    linear_kernel<<<N_NODES / 64, 256, L_SMEM>>>(x, W, b);
    dim3 grid(N_NODES / 128, KSPLIT);
    agg_kernel<<<grid, 256, SMEM_BYTES>>>(adj);
    reduce_kernel<<<N_NODES * OUT_F / 4 / 256, 256>>>(out);
}